// round 1
// baseline (speedup 1.0000x reference)
#include <cuda_runtime.h>
#include <cuda_bf16.h>

#define B_  32
#define C_  256
#define HW_ 64
#define AS_ 8
#define T_  64   // AS*AS

// ---------------- scratch (device globals; every element rewritten each call) ----------------
__device__ float g_PR[B_ * C_ * T_];        // pooled F_rgb  [b][c][t]
__device__ float g_PD[B_ * C_ * T_];        // pooled F_d    [b][c][t]
__device__ float g_Q [B_ * C_ * T_];
__device__ float g_K [B_ * C_ * T_];
__device__ float g_V [B_ * C_ * T_];
__device__ float g_Apart[8 * B_ * T_ * T_]; // partial A per c-slice
__device__ float g_A [B_ * T_ * T_];        // softmaxed A [b][t][s]
__device__ float g_F [B_ * C_ * T_];        // Fatt [b][c][t]

// ---------------- 1) 8x8 avg pool of both inputs ----------------
// grid: 2*B*C blocks, 128 threads. Each block pools one 64x64 plane to 8x8.
__global__ void pool_kernel(const float* __restrict__ Frgb, const float* __restrict__ Fd) {
    int bid   = blockIdx.x;
    int which = bid >> 13;            // 0: rgb, 1: d   (8192 planes each)
    int plane = bid & 8191;           // b*C + c
    const float* src = (which ? Fd : Frgb) + (size_t)plane * (HW_ * HW_);
    float* dst = (which ? g_PD : g_PR) + (size_t)plane * T_;

    __shared__ float part[128];
    int t = threadIdx.x;              // 128 threads
    int chunk = t & 15;               // which float4 along w (16 * 4 = 64)
    int i     = t >> 4;               // pooled row 0..7
    const float4* p = (const float4*)src;
    float s = 0.f;
#pragma unroll
    for (int r = 0; r < 8; r++) {
        float4 v = p[(i * 8 + r) * 16 + chunk];
        s += (v.x + v.y) + (v.z + v.w);
    }
    part[t] = s;
    __syncthreads();
    if (t < 64) {
        int pi = t >> 3, pj = t & 7;
        dst[t] = (part[pi * 16 + 2 * pj] + part[pi * 16 + 2 * pj + 1]) * (1.0f / 64.0f);
    }
}

// ---------------- 2) QKV projections: Out[b][o][t] = sum_c W[o][c] * P[b][c][t] + bias[o] ----------------
// grid: (B, 4 m-tiles of 64, 3 matrices), 256 threads, 4x4 micro-tile.
__global__ void qkv_kernel(const float* __restrict__ Wq, const float* __restrict__ bq,
                           const float* __restrict__ Wk, const float* __restrict__ bk,
                           const float* __restrict__ Wv, const float* __restrict__ bv) {
    int b  = blockIdx.x;
    int o0 = blockIdx.y * 64;
    int z  = blockIdx.z;
    const float* W; const float* bias; const float* P; float* Out;
    if (z == 0)      { W = Wq; bias = bq; P = g_PR; Out = g_Q; }
    else if (z == 1) { W = Wk; bias = bk; P = g_PD; Out = g_K; }
    else             { W = Wv; bias = bv; P = g_PD; Out = g_V; }

    __shared__ float Ws[64][33];   // [m][k], padded: conflict-free scalar reads
    __shared__ float Xs[32][64];   // [k][t]

    int tid = threadIdx.x;
    int m0 = (tid >> 4) * 4;       // 16 m-groups
    int n0 = (tid & 15) * 4;       // 16 n-groups
    float acc[4][4] = {};

    const float* Pb = P + ((size_t)b * C_ * T_);

    for (int kc = 0; kc < C_; kc += 32) {
        // load W tile [64][32] (scalar smem stores into padded rows)
#pragma unroll
        for (int q = 0; q < 2; q++) {
            int l = tid + q * 256;            // 0..511 (512 float4)
            int row = l >> 3, c4 = l & 7;
            float4 v = *(const float4*)&W[(o0 + row) * C_ + kc + c4 * 4];
            Ws[row][c4 * 4 + 0] = v.x; Ws[row][c4 * 4 + 1] = v.y;
            Ws[row][c4 * 4 + 2] = v.z; Ws[row][c4 * 4 + 3] = v.w;
        }
        // load X tile [32][64]
#pragma unroll
        for (int q = 0; q < 2; q++) {
            int l = tid + q * 256;            // 0..511
            int row = l >> 4, c4 = l & 15;
            *(float4*)&Xs[row][c4 * 4] = *(const float4*)&Pb[(kc + row) * T_ + c4 * 4];
        }
        __syncthreads();
#pragma unroll
        for (int k = 0; k < 32; k++) {
            float a0 = Ws[m0 + 0][k], a1 = Ws[m0 + 1][k], a2 = Ws[m0 + 2][k], a3 = Ws[m0 + 3][k];
            float4 bv4 = *(const float4*)&Xs[k][n0];
            float bb[4] = {bv4.x, bv4.y, bv4.z, bv4.w};
#pragma unroll
            for (int j = 0; j < 4; j++) {
                acc[0][j] = fmaf(a0, bb[j], acc[0][j]);
                acc[1][j] = fmaf(a1, bb[j], acc[1][j]);
                acc[2][j] = fmaf(a2, bb[j], acc[2][j]);
                acc[3][j] = fmaf(a3, bb[j], acc[3][j]);
            }
        }
        __syncthreads();
    }

    float* Ob = Out + ((size_t)b * C_ * T_);
#pragma unroll
    for (int i = 0; i < 4; i++) {
        float bbv = bias[o0 + m0 + i];
        float4 r;
        r.x = acc[i][0] + bbv; r.y = acc[i][1] + bbv;
        r.z = acc[i][2] + bbv; r.w = acc[i][3] + bbv;
        *(float4*)&Ob[(o0 + m0 + i) * T_ + n0] = r;
    }
}

// ---------------- 3) partial A: A_p[t][s] = sum_{c in slice} Q[c][t] K[c][s] ----------------
// grid: (B, 8 slices of 32 channels), 256 threads, 4x4 micro-tile.
__global__ void attn_partial_kernel() {
    int b = blockIdx.x;
    int kc0 = blockIdx.y * 32;
    __shared__ float Qs[32][64];
    __shared__ float Ks[32][64];
    int tid = threadIdx.x;
    const float* Qb = g_Q + ((size_t)b * C_ * T_);
    const float* Kb = g_K + ((size_t)b * C_ * T_);
#pragma unroll
    for (int q = 0; q < 2; q++) {
        int l = tid + q * 256; int row = l >> 4, c4 = l & 15;
        *(float4*)&Qs[row][c4 * 4] = *(const float4*)&Qb[(kc0 + row) * T_ + c4 * 4];
    }
#pragma unroll
    for (int q = 0; q < 2; q++) {
        int l = tid + q * 256; int row = l >> 4, c4 = l & 15;
        *(float4*)&Ks[row][c4 * 4] = *(const float4*)&Kb[(kc0 + row) * T_ + c4 * 4];
    }
    __syncthreads();
    int t0 = (tid >> 4) * 4, s0 = (tid & 15) * 4;
    float acc[4][4] = {};
#pragma unroll
    for (int k = 0; k < 32; k++) {
        float4 qv = *(const float4*)&Qs[k][t0];
        float4 kv = *(const float4*)&Ks[k][s0];
        float qa[4] = {qv.x, qv.y, qv.z, qv.w};
        float ka[4] = {kv.x, kv.y, kv.z, kv.w};
#pragma unroll
        for (int i = 0; i < 4; i++)
#pragma unroll
            for (int j = 0; j < 4; j++)
                acc[i][j] = fmaf(qa[i], ka[j], acc[i][j]);
    }
    float* Ap = g_Apart + (((size_t)blockIdx.y * B_ + b) * (T_ * T_));
#pragma unroll
    for (int i = 0; i < 4; i++) {
        float4 r; r.x = acc[i][0]; r.y = acc[i][1]; r.z = acc[i][2]; r.w = acc[i][3];
        *(float4*)&Ap[(t0 + i) * T_ + s0] = r;
    }
}

// ---------------- 4) reduce partials + row softmax ----------------
// grid: B blocks, 256 threads.
__global__ void softmax_kernel() {
    int b = blockIdx.x;
    __shared__ float As[64][68];
    int tid = threadIdx.x;
#pragma unroll
    for (int q = 0; q < 4; q++) {
        int l = tid + q * 256;               // 1024 float4
        int row = l >> 4, c4 = l & 15;
        float4 s = {0.f, 0.f, 0.f, 0.f};
#pragma unroll
        for (int p = 0; p < 8; p++) {
            float4 v = *(const float4*)&g_Apart[((size_t)p * B_ + b) * (T_ * T_) + row * T_ + c4 * 4];
            s.x += v.x; s.y += v.y; s.z += v.z; s.w += v.w;
        }
        *(float4*)&As[row][c4 * 4] = s;
    }
    __syncthreads();
    int warp = tid >> 5, lane = tid & 31;
#pragma unroll
    for (int r8 = 0; r8 < 8; r8++) {
        int r = warp * 8 + r8;
        float v0 = As[r][lane], v1 = As[r][lane + 32];
        float m = fmaxf(v0, v1);
#pragma unroll
        for (int off = 16; off; off >>= 1) m = fmaxf(m, __shfl_xor_sync(0xffffffffu, m, off));
        float e0 = __expf(v0 - m), e1 = __expf(v1 - m);
        float s = e0 + e1;
#pragma unroll
        for (int off = 16; off; off >>= 1) s += __shfl_xor_sync(0xffffffffu, s, off);
        float inv = 1.0f / s;
        As[r][lane] = e0 * inv; As[r][lane + 32] = e1 * inv;
    }
    __syncthreads();
    float* Ab = g_A + ((size_t)b * T_ * T_);
#pragma unroll
    for (int q = 0; q < 4; q++) {
        int l = tid + q * 256;
        int row = l >> 4, c4 = l & 15;
        *(float4*)&Ab[row * T_ + c4 * 4] = *(const float4*)&As[row][c4 * 4];
    }
}

// ---------------- 5) Fatt[b][c][t] = sum_s V[b][c][s] * A[b][t][s] ----------------
// grid: (B, 8 chunks of 32 channels), 256 threads.
__global__ void fatt_kernel() {
    int b = blockIdx.x, cc = blockIdx.y;
    __shared__ float As[64][68];
    __shared__ float Vs[32][64];
    int tid = threadIdx.x;
    const float* Ab = g_A + ((size_t)b * T_ * T_);
#pragma unroll
    for (int q = 0; q < 4; q++) {
        int l = tid + q * 256;
        int row = l >> 4, c4 = l & 15;
        *(float4*)&As[row][c4 * 4] = *(const float4*)&Ab[row * T_ + c4 * 4];
    }
    const float* Vb = g_V + ((size_t)b * C_ * T_) + (size_t)cc * 32 * T_;
#pragma unroll
    for (int q = 0; q < 2; q++) {
        int l = tid + q * 256;
        int row = l >> 4, c4 = l & 15;
        *(float4*)&Vs[row][c4 * 4] = *(const float4*)&Vb[row * T_ + c4 * 4];
    }
    __syncthreads();
    int cl = tid >> 3;             // 0..31 channel within chunk
    int t0 = tid & 7;              // t = t0 + 8*j  (stride-8 -> conflict-free smem reads)
    float acc[8] = {};
#pragma unroll
    for (int s4 = 0; s4 < 16; s4++) {
        float4 v = *(const float4*)&Vs[cl][s4 * 4];
#pragma unroll
        for (int j = 0; j < 8; j++) {
            float4 a = *(const float4*)&As[t0 + 8 * j][s4 * 4];
            acc[j] = fmaf(v.x, a.x, acc[j]);
            acc[j] = fmaf(v.y, a.y, acc[j]);
            acc[j] = fmaf(v.z, a.z, acc[j]);
            acc[j] = fmaf(v.w, a.w, acc[j]);
        }
    }
    float* Fb = g_F + ((size_t)b * C_ * T_) + (size_t)(cc * 32 + cl) * T_;
#pragma unroll
    for (int j = 0; j < 8; j++) Fb[t0 + 8 * j] = acc[j];
}

// ---------------- 6) bilinear upsample (half-pixel, edge-renormalized == clamp) + blend ----------------
// grid: B*C blocks, 256 threads (one 64x64 plane each).
__global__ void upsample_blend_kernel(const float* __restrict__ Frgb,
                                      const float* __restrict__ alphap,
                                      float* __restrict__ out) {
    int plane = blockIdx.x;
    __shared__ float Fs[64];
    __shared__ int   i0s[64];
    __shared__ int   i1s[64];
    __shared__ float fs[64];
    int tid = threadIdx.x;
    if (tid < 64) {
        Fs[tid] = g_F[(size_t)plane * T_ + tid];
        float s  = (tid + 0.5f) * 0.125f - 0.5f;
        float fl = floorf(s);
        int   i0 = (int)fl;
        fs[tid]  = s - fl;
        i0s[tid] = i0 < 0 ? 0 : i0;
        i1s[tid] = (i0 + 1) > 7 ? 7 : (i0 + 1);
    }
    __syncthreads();
    float alpha = *alphap;
    float beta  = 1.0f - alpha;
    const float* rp = Frgb + (size_t)plane * (HW_ * HW_);
    float*       op = out  + (size_t)plane * (HW_ * HW_);
#pragma unroll
    for (int q = 0; q < 16; q++) {
        int idx = tid + q * 256;
        int h = idx >> 6, w = idx & 63;
        int   y0 = i0s[h], y1 = i1s[h]; float fy = fs[h];
        int   x0 = i0s[w], x1 = i1s[w]; float fx = fs[w];
        float v00 = Fs[y0 * 8 + x0], v01 = Fs[y0 * 8 + x1];
        float v10 = Fs[y1 * 8 + x0], v11 = Fs[y1 * 8 + x1];
        float top = v00 + fx * (v01 - v00);
        float bot = v10 + fx * (v11 - v10);
        float v   = top + fy * (bot - top);
        op[idx] = alpha * v + beta * rp[idx];
    }
}

// ---------------- launch ----------------
extern "C" void kernel_launch(void* const* d_in, const int* in_sizes, int n_in,
                              void* d_out, int out_size) {
    const float* Frgb  = (const float*)d_in[0];
    const float* Fd    = (const float*)d_in[1];
    const float* Wq    = (const float*)d_in[2];
    const float* bq    = (const float*)d_in[3];
    const float* Wk    = (const float*)d_in[4];
    const float* bk    = (const float*)d_in[5];
    const float* Wv    = (const float*)d_in[6];
    const float* bv    = (const float*)d_in[7];
    const float* alpha = (const float*)d_in[8];
    float* out = (float*)d_out;

    pool_kernel<<<2 * B_ * C_, 128>>>(Frgb, Fd);
    qkv_kernel<<<dim3(B_, 4, 3), 256>>>(Wq, bq, Wk, bk, Wv, bv);
    attn_partial_kernel<<<dim3(B_, 8), 256>>>();
    softmax_kernel<<<B_, 256>>>();
    fatt_kernel<<<dim3(B_, 8), 256>>>();
    upsample_blend_kernel<<<B_ * C_, 256>>>(Frgb, alpha, out);
}